// round 3
// baseline (speedup 1.0000x reference)
#include <cuda_runtime.h>

// EPLoss edit-probability DP, anti-diagonal wavefront, one warp per batch item.
// Shapes fixed by the problem: B=128, n_y=512, n_T=128, C=128. EOS label = 1.
//
// Recurrence (i>=1, j>=1):
//   ep[i,j] = ep[i-1,j-1]*pC(i-1,j-1) + ep[i-1,j]*pI(i-1,j) + ep[i,j-1]*pD(i,j-1)
//   pC(i,j) = R0[j]*pred[b,j,t_i]
//   pI(i,j) = Rins[j]*I[b,j,t_i],  Rins[j] = (j==n_y-1) ? 1 : R1[j]
//   pD(i,j) = (t_i==EOS) ? 1 : R2[j]
// Row 0:    ep[0,0]=1; ep[0,j] = ep[0,j-1] * ((t_0==EOS)?1:R2[j])
// Col 0:    ep[i,0] = ep[i-1,0] * Rins[1]*I[b,1,t_{i-1}]
// Output:   ep[n_T-1, n_y-1] per b.
//
// Mapping: lane L owns rows 4L..4L+3. At global step s, lane L computes column
// j = s - L (skew 1). ep[4L-1, j] / ep[4L-1, j-1] arrive via one shfl_up per
// step (current + previous step's shuffled value). Coefficient gathers are
// prefetched DPF steps ahead through a fully-unrolled register ring.

#define NB 128
#define NY 512
#define NT 128
#define CC 128
#define DPF 8

__global__ __launch_bounds__(32, 1)
void ep_wavefront(const float* __restrict__ pred,
                  const float* __restrict__ R,
                  const float* __restrict__ Iins,
                  const int* __restrict__ target,
                  float* __restrict__ out) {
    __shared__ float4 Rs[NY];   // {R0[j], Rins[j], R2[j], 0}

    const int b    = blockIdx.x;
    const int lane = threadIdx.x;

    const float* __restrict__ predb = pred + (size_t)b * NY * CC;
    const float* __restrict__ Ib    = Iins + (size_t)b * NY * CC;
    const float* __restrict__ Rb    = R    + (size_t)b * NY * 3;
    const int*   __restrict__ tb    = target + b * NT;

    // Pack R into shared as float4 rows (one LDS.128 per step later).
    for (int j = lane; j < NY; j += 32) {
        float r0 = Rb[3 * j + 0];
        float r1 = Rb[3 * j + 1];
        float r2 = Rb[3 * j + 2];
        Rs[j] = make_float4(r0, (j == NY - 1) ? 1.0f : r1, r2, 0.0f);
    }
    __syncthreads();

    const int r0row = lane * 4;
    // t for the 4 owned rows (used by pD), and t_{i-1} for coefficients.
    const int tt0 = tb[r0row + 0];
    const int tt1 = tb[r0row + 1];
    const int tt2 = tb[r0row + 2];
    const int tt3 = tb[r0row + 3];
    const int tc0 = (lane == 0) ? 0 : tb[r0row - 1];  // unused on lane 0
    const int tc1 = tt0, tc2 = tt1, tc3 = tt2;

    const bool e0 = (tt0 == 1), e1 = (tt1 == 1), e2 = (tt2 == 1), e3 = (tt3 == 1);
    const bool eRow0 = (tb[0] == 1);

    // Per-row base pointers for the gathers (class index folded in).
    const float* __restrict__ pp0 = predb + tc0;
    const float* __restrict__ pp1 = predb + tc1;
    const float* __restrict__ pp2 = predb + tc2;
    const float* __restrict__ pp3 = predb + tc3;
    const float* __restrict__ qi0 = Ib + tc0;
    const float* __restrict__ qi1 = Ib + tc1;
    const float* __restrict__ qi2 = Ib + tc2;
    const float* __restrict__ qi3 = Ib + tc3;

    // Column-0 coefficients hoisted: pI(i-1, 1) = Rins[1]*I[b,1,t_{i-1}]
    const float rins1 = Rb[3 * 1 + 1];
    const float pI1_0 = rins1 * Ib[CC + tc0];
    const float pI1_1 = rins1 * Ib[CC + tc1];
    const float pI1_2 = rins1 * Ib[CC + tc2];
    const float pI1_3 = rins1 * Ib[CC + tc3];

    // Prefetch ring: slot d holds gathers for the column used at step s (s%DPF==d).
    float fP[DPF][4], fI[DPF][4];
#pragma unroll
    for (int d = 0; d < DPF; ++d) {
        int c = d - lane;
        c = (c < 1) ? 1 : c;
        c = (c > NY - 1) ? (NY - 1) : c;
        const int oP = (c - 1) * CC;
        const int oI = c * CC;
        fP[d][0] = pp0[oP]; fP[d][1] = pp1[oP]; fP[d][2] = pp2[oP]; fP[d][3] = pp3[oP];
        fI[d][0] = qi0[oI]; fI[d][1] = qi1[oI]; fI[d][2] = qi2[oI]; fI[d][3] = qi3[oI];
    }

    float cur0 = 0.f, cur1 = 0.f, cur2 = 0.f, cur3 = 0.f;
    float carry = 0.f;   // cur3 as of end of previous step (shuffled down)
    float upp   = 0.f;   // shfl result from previous step = ep[r0-1, j-1]
    float rpx   = 0.f;   // R0[j-1]
    float rpz   = 0.f;   // R2[j-1]

    // 544 steps (512 + 32, padded to a multiple of DPF); step 543 is inert.
    for (int sb = 0; sb < NY + 32; sb += DPF) {
#pragma unroll
        for (int d = 0; d < DPF; ++d) {
            const int s = sb + d;
            const float upc = __shfl_up_sync(0xffffffffu, carry, 1); // ep[r0-1, j]
            const int j = s - lane;
            if (j >= 0 && j < NY) {
                const float4 rj = Rs[j];
                if (j == 0) {
                    cur0 = lane ? (upc * pI1_0) : 1.0f;
                    cur1 = cur0 * pI1_1;
                    cur2 = cur1 * pI1_2;
                    cur3 = cur2 * pI1_3;
                } else {
                    const float rins = rj.y;
                    const float pd0 = e0 ? 1.0f : rpz;
                    const float pd1 = e1 ? 1.0f : rpz;
                    const float pd2 = e2 ? 1.0f : rpz;
                    const float pd3 = e3 ? 1.0f : rpz;
                    float n0;
                    if (lane == 0) {
                        // row 0 cumprod: ep[0,j] = ep[0,j-1] * ((t0==EOS)?1:R2[j])
                        n0 = cur0 * (eRow0 ? 1.0f : rj.z);
                    } else {
                        n0 = upp * (rpx * fP[d][0])
                           + upc * (rins * fI[d][0])
                           + cur0 * pd0;
                    }
                    const float n1 = cur0 * (rpx * fP[d][1]) + n0 * (rins * fI[d][1]) + cur1 * pd1;
                    const float n2 = cur1 * (rpx * fP[d][2]) + n1 * (rins * fI[d][2]) + cur2 * pd2;
                    const float n3 = cur2 * (rpx * fP[d][3]) + n2 * (rins * fI[d][3]) + cur3 * pd3;
                    cur0 = n0; cur1 = n1; cur2 = n2; cur3 = n3;
                }
                rpx = rj.x;
                rpz = rj.z;
            }
            upp   = upc;
            carry = cur3;

            // Refill slot d with column (s + DPF - lane), clamped to [1, NY-1].
            int c = s + DPF - lane;
            c = (c < 1) ? 1 : c;
            c = (c > NY - 1) ? (NY - 1) : c;
            const int oP = (c - 1) * CC;
            const int oI = c * CC;
            fP[d][0] = pp0[oP]; fP[d][1] = pp1[oP]; fP[d][2] = pp2[oP]; fP[d][3] = pp3[oP];
            fI[d][0] = qi0[oI]; fI[d][1] = qi1[oI]; fI[d][2] = qi2[oI]; fI[d][3] = qi3[oI];
        }
    }

    if (lane == 31) out[b] = cur3;
}

extern "C" void kernel_launch(void* const* d_in, const int* in_sizes, int n_in,
                              void* d_out, int out_size) {
    const float* pred   = (const float*)d_in[0];
    const float* R      = (const float*)d_in[1];
    const float* Iins   = (const float*)d_in[2];
    const int*   target = (const int*)d_in[3];
    float* out = (float*)d_out;

    const int B = out_size;  // one output per batch item (128)
    ep_wavefront<<<B, 32>>>(pred, R, Iins, target, out);
}

// round 4
// speedup vs baseline: 1.0780x; 1.0780x over previous
#include <cuda_runtime.h>

// EPLoss edit-probability DP, anti-diagonal wavefront, one warp per batch item.
// B=128, n_y=512, n_T=128, C=128. EOS label = 1.
//
// R3 change: the per-step coefficient gathers were 8 per-lane-random scalar
// LDGs (~32 lines each -> ~256 L1tex wavefronts/step, the measured bottleneck).
// Now whole coefficient rows are staged into a shared-memory ring with
// cp.async (2 coalesced 512B row copies per step), and the per-lane random
// gathers become LDS from shared. Prefetch distance DELTA steps covers DRAM.

#define NY 512
#define NT 128
#define CC 128
#define RING 64          // ring slots (power of 2)
#define PADW 132         // floats per staged row (128 + 4 pad: decorrelates banks)
#define PADB (PADW * 4)  // 528 bytes per slot row
#define DELTA 12         // prefetch distance in steps
#define UNR 4            // steps per wait/sync block
#define TOT 544          // NY + 32 steps (multiple of UNR)

__global__ __launch_bounds__(32, 1)
void ep_wavefront(const float* __restrict__ pred,
                  const float* __restrict__ R,
                  const float* __restrict__ Iins,
                  const int* __restrict__ target,
                  float* __restrict__ out) {
    extern __shared__ float smem[];
    float*  ringP = smem;                       // [RING][PADW]: pred[b, c-1, :] for column c
    float*  ringI = smem + RING * PADW;         // [RING][PADW]: I[b, c, :]
    float4* Rs    = (float4*)(smem + 2 * RING * PADW);  // [NY]: {R0, Rins, R2, 0}

    const int b    = blockIdx.x;
    const int lane = threadIdx.x;

    const float* __restrict__ predb = pred + (size_t)b * NY * CC;
    const float* __restrict__ Ib    = Iins + (size_t)b * NY * CC;
    const float* __restrict__ Rb    = R    + (size_t)b * NY * 3;
    const int*   __restrict__ tb    = target + b * NT;

    const unsigned ringPs = (unsigned)__cvta_generic_to_shared(ringP);
    const unsigned ringIs = (unsigned)__cvta_generic_to_shared(ringI);

    // ---- Prologue staging: columns 1..DELTA-1, one commit group per column ----
#pragma unroll
    for (int c = 1; c < DELTA; ++c) {
        const unsigned dP = ringPs + (unsigned)((c & (RING - 1)) * PADB + lane * 16);
        const unsigned dI = ringIs + (unsigned)((c & (RING - 1)) * PADB + lane * 16);
        const float* sP = predb + (c - 1) * CC + lane * 4;
        const float* sI = Ib + c * CC + lane * 4;
        asm volatile("cp.async.cg.shared.global [%0], [%1], 16;" :: "r"(dP), "l"(sP));
        asm volatile("cp.async.cg.shared.global [%0], [%1], 16;" :: "r"(dI), "l"(sI));
        asm volatile("cp.async.commit_group;" ::: "memory");
    }

    // Pack R into shared as float4 rows.
    for (int j = lane; j < NY; j += 32) {
        float r0 = Rb[3 * j + 0];
        float r1 = Rb[3 * j + 1];
        float r2 = Rb[3 * j + 2];
        Rs[j] = make_float4(r0, (j == NY - 1) ? 1.0f : r1, r2, 0.0f);
    }

    const int r0row = lane * 4;
    const int tt0 = tb[r0row + 0];
    const int tt1 = tb[r0row + 1];
    const int tt2 = tb[r0row + 2];
    const int tt3 = tb[r0row + 3];
    const int tc0 = (lane == 0) ? 0 : tb[r0row - 1];  // unused on lane 0
    const int tc1 = tt0, tc2 = tt1, tc3 = tt2;

    const bool e0 = (tt0 == 1), e1 = (tt1 == 1), e2 = (tt2 == 1), e3 = (tt3 == 1);
    const bool eRow0 = (tb[0] == 1);

    // Column-0 coefficients hoisted: pI(i-1, 1) = Rins[1]*I[b,1,t_{i-1}]
    const float rins1 = Rb[3 * 1 + 1];
    const float pI1_0 = rins1 * Ib[CC + tc0];
    const float pI1_1 = rins1 * Ib[CC + tc1];
    const float pI1_2 = rins1 * Ib[CC + tc2];
    const float pI1_3 = rins1 * Ib[CC + tc3];

    __syncwarp();  // Rs stores visible before first read

    float cur0 = 0.f, cur1 = 0.f, cur2 = 0.f, cur3 = 0.f;
    float carry = 0.f;   // cur3 at end of previous step (shuffled up)
    float upp   = 0.f;   // previous step's shfl result = ep[r0-1, j-1]
    float rpx   = 0.f;   // R0[j-1]
    float rpz   = 0.f;   // R2[j-1]

    for (int sb = 0; sb < TOT; sb += UNR) {
        // Guarantee columns <= sb+UNR-1 staged (group index == column index):
        // committed so far = (DELTA-1) + sb; allow DELTA-UNR pending.
        asm volatile("cp.async.wait_group 8;" ::: "memory");
        __syncwarp();
#pragma unroll
        for (int d = 0; d < UNR; ++d) {
            const int s = sb + d;

            // Stage column s+DELTA (clamped; redundant tail loads are harmless).
            {
                const int cs   = s + DELTA;
                const int slot = cs & (RING - 1);
                const int c    = (cs < NY - 1) ? cs : (NY - 1);
                const unsigned dP = ringPs + (unsigned)(slot * PADB + lane * 16);
                const unsigned dI = ringIs + (unsigned)(slot * PADB + lane * 16);
                const float* sP = predb + (c - 1) * CC + lane * 4;
                const float* sI = Ib + c * CC + lane * 4;
                asm volatile("cp.async.cg.shared.global [%0], [%1], 16;" :: "r"(dP), "l"(sP));
                asm volatile("cp.async.cg.shared.global [%0], [%1], 16;" :: "r"(dI), "l"(sI));
                asm volatile("cp.async.commit_group;" ::: "memory");
            }

            const float upc = __shfl_up_sync(0xffffffffu, carry, 1); // ep[r0-1, j]
            const int j = s - lane;
            if (j >= 0 && j < NY) {
                const float4 rj = Rs[j];
                if (j == 0) {
                    cur0 = lane ? (upc * pI1_0) : 1.0f;
                    cur1 = cur0 * pI1_1;
                    cur2 = cur1 * pI1_2;
                    cur3 = cur2 * pI1_3;
                } else {
                    const int slotc = j & (RING - 1);
                    const float* __restrict__ bP = ringP + slotc * PADW;
                    const float* __restrict__ bI = ringI + slotc * PADW;
                    const float g0 = bP[tc0], g1 = bP[tc1], g2 = bP[tc2], g3 = bP[tc3];
                    const float h0 = bI[tc0], h1 = bI[tc1], h2 = bI[tc2], h3 = bI[tc3];
                    const float rins = rj.y;
                    const float pd0 = e0 ? 1.0f : rpz;
                    const float pd1 = e1 ? 1.0f : rpz;
                    const float pd2 = e2 ? 1.0f : rpz;
                    const float pd3 = e3 ? 1.0f : rpz;
                    float n0;
                    if (lane == 0) {
                        // row 0 cumprod: ep[0,j] = ep[0,j-1] * ((t0==EOS)?1:R2[j])
                        n0 = cur0 * (eRow0 ? 1.0f : rj.z);
                    } else {
                        n0 = upp * (rpx * g0) + upc * (rins * h0) + cur0 * pd0;
                    }
                    const float n1 = cur0 * (rpx * g1) + n0 * (rins * h1) + cur1 * pd1;
                    const float n2 = cur1 * (rpx * g2) + n1 * (rins * h2) + cur2 * pd2;
                    const float n3 = cur2 * (rpx * g3) + n2 * (rins * h3) + cur3 * pd3;
                    cur0 = n0; cur1 = n1; cur2 = n2; cur3 = n3;
                }
                rpx = rj.x;
                rpz = rj.z;
            }
            upp   = upc;
            carry = cur3;
        }
    }

    if (lane == 31) out[b] = cur3;
}

static const int kSmemBytes = 2 * RING * PADW * 4 + NY * 16;  // 75,776 B

extern "C" void kernel_launch(void* const* d_in, const int* in_sizes, int n_in,
                              void* d_out, int out_size) {
    const float* pred   = (const float*)d_in[0];
    const float* R      = (const float*)d_in[1];
    const float* Iins   = (const float*)d_in[2];
    const int*   target = (const int*)d_in[3];
    float* out = (float*)d_out;

    cudaFuncSetAttribute(ep_wavefront,
                         cudaFuncAttributeMaxDynamicSharedMemorySize, kSmemBytes);

    const int B = out_size;  // 128
    ep_wavefront<<<B, 32, kSmemBytes>>>(pred, R, Iins, target, out);
}

// round 7
// speedup vs baseline: 2.2368x; 2.0749x over previous
#include <cuda_runtime.h>

// EPLoss edit-probability DP, anti-diagonal wavefront, one warp per batch item.
// B=128, n_y=512, n_T=128, C=128. EOS label = 1.
//
// R4 change: the kernel is issue-bound at 1 warp/SM (issue=23.2% ~ single-warp
// ceiling). The per-step divergent branches (j-range, j==0, lane==0) each cost
// a BSSY/BSYNC envelope. Fix: peel into ramp(32) / steady(480) / epi(32);
// steady phase is fully branch-free — lane 0's special row-0 handling is done
// by gathering from a zeroed pad word (pC/pI contributions -> 0) plus one FSEL
// for pD. Coefficient rows staged via cp.async ring as in R3.

#define NY 512
#define NT 128
#define CC 128
#define RING 64          // ring slots (power of 2)
#define PADW 132         // 128 data + 4 pad floats (pad[0] == 0 used by lane 0)
#define PADB (PADW * 4)
#define DELTA 12         // prefetch distance in steps

__global__ __launch_bounds__(32, 1)
void ep_wavefront(const float* __restrict__ pred,
                  const float* __restrict__ R,
                  const float* __restrict__ Iins,
                  const int* __restrict__ target,
                  float* __restrict__ out) {
    extern __shared__ float smem[];
    float*  ringP = smem;                                // [RING][PADW]: pred[b, c-1, :]
    float*  ringI = smem + RING * PADW;                  // [RING][PADW]: I[b, c, :]
    float4* Rs    = (float4*)(smem + 2 * RING * PADW);   // [NY]: {R0, Rins, R2, 0}

    const int b    = blockIdx.x;
    const int lane = threadIdx.x;

    const float* __restrict__ predb = pred + (size_t)b * NY * CC;
    const float* __restrict__ Ib    = Iins + (size_t)b * NY * CC;
    const float* __restrict__ Rb    = R    + (size_t)b * NY * 3;
    const int*   __restrict__ tb    = target + b * NT;

    const unsigned ringPs = (unsigned)__cvta_generic_to_shared(ringP);
    const unsigned ringIs = (unsigned)__cvta_generic_to_shared(ringI);
    const unsigned laneOff = (unsigned)(lane * 16);
    const float* __restrict__ srcPb = predb + lane * 4;
    const float* __restrict__ srcIb = Ib + lane * 4;

    // Zero the pad words of every ring row (lane 0 gathers from pad -> 0).
    for (int k = lane; k < RING * 4; k += 32) {
        const int slot = k >> 2, w = k & 3;
        ringP[slot * PADW + CC + w] = 0.0f;
        ringI[slot * PADW + CC + w] = 0.0f;
    }

#define STAGE(S_) do {                                                          \
    const int cs_ = (S_) + DELTA;                                               \
    const int c_  = (cs_ < NY - 1) ? cs_ : (NY - 1);                            \
    const unsigned so_ = (unsigned)(cs_ & (RING - 1)) * PADB + laneOff;         \
    const float* sP_ = srcPb + (c_ - 1) * CC;                                   \
    const float* sI_ = srcIb + c_ * CC;                                         \
    asm volatile("cp.async.cg.shared.global [%0], [%1], 16;"                    \
                 :: "r"(ringPs + so_), "l"(sP_));                               \
    asm volatile("cp.async.cg.shared.global [%0], [%1], 16;"                    \
                 :: "r"(ringIs + so_), "l"(sI_));                               \
    asm volatile("cp.async.commit_group;" ::: "memory");                        \
} while (0)

    // Prologue staging: columns 1..DELTA-1 (one commit group per column).
#pragma unroll
    for (int c = 1; c < DELTA; ++c) {
        const unsigned so = (unsigned)(c & (RING - 1)) * PADB + laneOff;
        const float* sP = srcPb + (c - 1) * CC;
        const float* sI = srcIb + c * CC;
        asm volatile("cp.async.cg.shared.global [%0], [%1], 16;" :: "r"(ringPs + so), "l"(sP));
        asm volatile("cp.async.cg.shared.global [%0], [%1], 16;" :: "r"(ringIs + so), "l"(sI));
        asm volatile("cp.async.commit_group;" ::: "memory");
    }

    // Pack R into shared as float4 rows.
    for (int j = lane; j < NY; j += 32) {
        const float r0 = Rb[3 * j + 0];
        const float r1 = Rb[3 * j + 1];
        const float r2 = Rb[3 * j + 2];
        Rs[j] = make_float4(r0, (j == NY - 1) ? 1.0f : r1, r2, 0.0f);
    }

    const int r0row = lane * 4;
    const int tt0 = tb[r0row + 0];
    const int tt1 = tb[r0row + 1];
    const int tt2 = tb[r0row + 2];
    const int tt3 = tb[r0row + 3];
    // Gather indices: tg0 is t_{row-1}; lane 0 points at the zero pad word.
    const int tg0 = lane ? tb[r0row - 1] : CC;
    const int tg1 = tt0, tg2 = tt1, tg3 = tt2;
    const bool e0 = (tt0 == 1), e1 = (tt1 == 1), e2 = (tt2 == 1), e3 = (tt3 == 1);
    const bool isl0 = (lane == 0);

    // Column-0 coefficients hoisted: pI(i-1, 1) = Rins[1]*I[b,1,t_{i-1}]
    const float rins1 = Rb[3 * 1 + 1];
    const float pI1_0 = rins1 * Ib[CC + (lane ? tb[r0row - 1] : 0)];  // unused on lane 0
    const float pI1_1 = rins1 * Ib[CC + tg1];
    const float pI1_2 = rins1 * Ib[CC + tg2];
    const float pI1_3 = rins1 * Ib[CC + tg3];

    __syncwarp();  // pads + Rs visible

    float cur0 = 0.f, cur1 = 0.f, cur2 = 0.f, cur3 = 0.f;
    float carry = 0.f;   // cur3 at end of previous step
    float upp   = 0.f;   // previous step's shfl result = ep[r0-1, j-1]
    float rpx   = 0.f;   // R0[j-1]
    float rpz   = 0.f;   // R2[j-1]

    // Unified j>=1 body. Lane 0: g0=h0=0 (pad word) -> n0 = cur0 * pd0 with
    // pd0 = e0 ? 1 : R2[j]  == row-0 cumprod. Chain: n_{k} = fmaf(n_{k-1}, rh_k, c_k).
#define BODY(J_, UPC_) do {                                                     \
    const int slotc_ = (J_) & (RING - 1);                                       \
    const float* __restrict__ bP_ = ringP + slotc_ * PADW;                      \
    const float* __restrict__ bI_ = ringI + slotc_ * PADW;                      \
    const float g0_ = bP_[tg0], g1_ = bP_[tg1], g2_ = bP_[tg2], g3_ = bP_[tg3]; \
    const float h0_ = bI_[tg0], h1_ = bI_[tg1], h2_ = bI_[tg2], h3_ = bI_[tg3]; \
    const float4 rj_ = Rs[(J_)];                                                \
    const float rins_ = rj_.y;                                                  \
    const float pz0_ = isl0 ? rj_.z : rpz;                                      \
    const float pd0_ = e0 ? 1.0f : pz0_;                                        \
    const float pd1_ = e1 ? 1.0f : rpz;                                         \
    const float pd2_ = e2 ? 1.0f : rpz;                                         \
    const float pd3_ = e3 ? 1.0f : rpz;                                         \
    const float rg0_ = rpx * g0_, rg1_ = rpx * g1_;                             \
    const float rg2_ = rpx * g2_, rg3_ = rpx * g3_;                             \
    const float rh0_ = rins_ * h0_, rh1_ = rins_ * h1_;                         \
    const float rh2_ = rins_ * h2_, rh3_ = rins_ * h3_;                         \
    const float c0_ = fmaf(upp,  rg0_, cur0 * pd0_);                            \
    const float n0_ = fmaf((UPC_), rh0_, c0_);                                  \
    const float c1_ = fmaf(cur0, rg1_, cur1 * pd1_);                            \
    const float n1_ = fmaf(n0_, rh1_, c1_);                                     \
    const float c2_ = fmaf(cur1, rg2_, cur2 * pd2_);                            \
    const float n2_ = fmaf(n1_, rh2_, c2_);                                     \
    const float c3_ = fmaf(cur2, rg3_, cur3 * pd3_);                            \
    const float n3_ = fmaf(n2_, rh3_, c3_);                                     \
    cur0 = n0_; cur1 = n1_; cur2 = n2_; cur3 = n3_;                             \
    rpx = rj_.x; rpz = rj_.z;                                                   \
} while (0)

#define RAMP_STEP(S_) do {                                                      \
    STAGE(S_);                                                                  \
    const float upc_ = __shfl_up_sync(0xffffffffu, carry, 1);                   \
    const int j_ = (S_) - lane;                                                 \
    if (j_ >= 0) {                                                              \
        if (j_ == 0) {                                                          \
            cur0 = lane ? (upc_ * pI1_0) : 1.0f;                                \
            cur1 = cur0 * pI1_1;                                                \
            cur2 = cur1 * pI1_2;                                                \
            cur3 = cur2 * pI1_3;                                                \
            const float4 r0_ = Rs[0];                                           \
            rpx = r0_.x; rpz = r0_.z;                                           \
        } else {                                                                \
            BODY(j_, upc_);                                                     \
        }                                                                       \
    }                                                                           \
    upp = upc_; carry = cur3;                                                   \
} while (0)

#define STEADY_STEP(S_) do {                                                    \
    STAGE(S_);                                                                  \
    const float upc_ = __shfl_up_sync(0xffffffffu, carry, 1);                   \
    BODY((S_) - lane, upc_);                                                    \
    upp = upc_; carry = cur3;                                                   \
} while (0)

#define EPI_STEP(S_) do {                                                       \
    const float upc_ = __shfl_up_sync(0xffffffffu, carry, 1);                   \
    const int j_ = (S_) - lane;                                                 \
    if (j_ < NY) { BODY(j_, upc_); }                                            \
    upp = upc_; carry = cur3;                                                   \
} while (0)

    // Ramp-up: s in [0, 32). j = s-lane may be <0 or 0.
    for (int sb = 0; sb < 32; sb += 4) {
        asm volatile("cp.async.wait_group 8;" ::: "memory");
        __syncwarp();
        RAMP_STEP(sb + 0); RAMP_STEP(sb + 1); RAMP_STEP(sb + 2); RAMP_STEP(sb + 3);
    }

    // Steady: s in [32, 512). All lanes j in [1, 511] — branch-free.
    for (int sb = 32; sb < NY; sb += 4) {
        asm volatile("cp.async.wait_group 8;" ::: "memory");
        __syncwarp();
        STEADY_STEP(sb + 0); STEADY_STEP(sb + 1); STEADY_STEP(sb + 2); STEADY_STEP(sb + 3);
    }

    // Epilogue: s in [512, 544). All columns already staged; no more staging.
    asm volatile("cp.async.wait_group 0;" ::: "memory");
    __syncwarp();
    for (int s = NY; s < NY + 32; ++s) {
        EPI_STEP(s);
    }

    if (lane == 31) out[b] = cur3;
}

static const int kSmemBytes = 2 * RING * PADW * 4 + NY * 16;  // 75,776 B

extern "C" void kernel_launch(void* const* d_in, const int* in_sizes, int n_in,
                              void* d_out, int out_size) {
    const float* pred   = (const float*)d_in[0];
    const float* R      = (const float*)d_in[1];
    const float* Iins   = (const float*)d_in[2];
    const int*   target = (const int*)d_in[3];
    float* out = (float*)d_out;

    cudaFuncSetAttribute(ep_wavefront,
                         cudaFuncAttributeMaxDynamicSharedMemorySize, kSmemBytes);

    const int B = out_size;  // 128
    ep_wavefront<<<B, 32, kSmemBytes>>>(pred, R, Iins, target, out);
}